// round 17
// baseline (speedup 1.0000x reference)
#include <cuda_runtime.h>
#include <cuda_bf16.h>

#define N_NODES 100000

// Scratch (zero-init at load). Replay invariant: deg=0 at entry (k_prep
// cleaned it); dinv/dw/y/p rewritten by k_prep; S zeroed by k_deg.
// Hot paths identical to the best-measured config (R16, 78.3us). This round:
// explicit PDL triggers fire as soon as every block has ISSUED its work
// (REDs are fire-and-forget), so the dependent kernel's prologue overlaps
// the predecessor's LTS drain phase. cudaGridDependencySynchronize() still
// gates all scratch access — semantics unchanged.
__device__ float  g_deg [N_NODES];
__device__ float  g_dinv[N_NODES];   // read-only during k_edge (gather stream)
__device__ float2 g_dw  [N_NODES];   // .x=dinv, .y=wacc; atomic-only during k_edge
__device__ float4 g_y   [N_NODES];   // x * dinv (pre-scaled source features)
__device__ float4 g_p   [N_NODES];   // seeded with y; += y[src] per edge
__device__ float  g_S   [64];        // sum_i w_i * relu(pfull_i @ W1 + b1)

// K1: in-degree count (dst half only), 4 edges/thread. Zeroes S.
__global__ void k_deg(const int4* __restrict__ dst4, int E4) {
    int t = blockIdx.x * blockDim.x + threadIdx.x;
    if (t < 64) g_S[t] = 0.0f;
    if (t < E4) {
        int4 d = dst4[t];
        if ((unsigned)d.x < (unsigned)N_NODES) atomicAdd(&g_deg[d.x], 1.0f);
        if ((unsigned)d.y < (unsigned)N_NODES) atomicAdd(&g_deg[d.y], 1.0f);
        if ((unsigned)d.z < (unsigned)N_NODES) atomicAdd(&g_deg[d.z], 1.0f);
        if ((unsigned)d.w < (unsigned)N_NODES) atomicAdd(&g_deg[d.w], 1.0f);
    }
    cudaTriggerProgrammaticLaunchCompletion();   // REDs issued; let k_prep launch
}

// K2: dinv = rsqrt(deg+1); y = x*dinv; seed p = y, dw = {dinv, dinv}.
// Resets deg. PDL: x load (input) pre-sync; g_deg access post-sync.
__global__ void k_prep(const float4* __restrict__ x) {
    int i = blockIdx.x * blockDim.x + threadIdx.x;
    float4 xv = make_float4(0.f, 0.f, 0.f, 0.f);
    if (i < N_NODES) xv = x[i];            // independent of k_deg
    cudaGridDependencySynchronize();       // wait for deg to be final
    if (i < N_NODES) {
        float di = rsqrtf(g_deg[i] + 1.0f);
        g_deg[i]  = 0.0f;                 // self-clean (line already owned)
        g_dinv[i] = di;
        g_dw[i]   = make_float2(di, di);  // wacc seeded with self-loop dinv
        float4 yv = make_float4(xv.x * di, xv.y * di, xv.z * di, xv.w * di);
        g_y[i] = yv;
        g_p[i] = yv;                      // p seeded with self-loop message
    }
    cudaTriggerProgrammaticLaunchCompletion();   // stores issued; let k_edge launch
}

// K3: fused edge pass, 4 edges/thread. PDL: index loads (inputs) pre-sync,
// overlapped under k_prep; gathers/REDs post-sync. Per edge:
//   p[d]    += y[s]      (RED.v4 f32, payload straight from the gather)
//   dw[s].y += dinv[d]   (RED scalar f32)
__global__ void k_edge(const int4* __restrict__ src4,
                       const int4* __restrict__ dst4,
                       int E4) {
    int t = blockIdx.x * blockDim.x + threadIdx.x;
    int4 s = {0,0,0,0}, d = {0,0,0,0};
    bool live = (t < E4);
    if (live) { s = src4[t]; d = dst4[t]; }  // independent of k_prep
    cudaGridDependencySynchronize();         // wait for y/dinv/dw/p seeds
    if (live) {
        bool ok0 = (unsigned)s.x < (unsigned)N_NODES && (unsigned)d.x < (unsigned)N_NODES;
        bool ok1 = (unsigned)s.y < (unsigned)N_NODES && (unsigned)d.y < (unsigned)N_NODES;
        bool ok2 = (unsigned)s.z < (unsigned)N_NODES && (unsigned)d.z < (unsigned)N_NODES;
        bool ok3 = (unsigned)s.w < (unsigned)N_NODES && (unsigned)d.w < (unsigned)N_NODES;
        float4 y0, y1, y2, y3;
        float nd0 = 0.f, nd1 = 0.f, nd2 = 0.f, nd3 = 0.f;
        if (ok0) { y0 = __ldg(&g_y[s.x]); nd0 = __ldg(&g_dinv[d.x]); }
        if (ok1) { y1 = __ldg(&g_y[s.y]); nd1 = __ldg(&g_dinv[d.y]); }
        if (ok2) { y2 = __ldg(&g_y[s.z]); nd2 = __ldg(&g_dinv[d.z]); }
        if (ok3) { y3 = __ldg(&g_y[s.w]); nd3 = __ldg(&g_dinv[d.w]); }
        if (ok0) {
            asm volatile("red.global.add.v4.f32 [%0], {%1, %2, %3, %4};"
                         :: "l"((float*)&g_p[d.x]),
                            "f"(y0.x), "f"(y0.y), "f"(y0.z), "f"(y0.w) : "memory");
            atomicAdd(&g_dw[s.x].y, nd0);
        }
        if (ok1) {
            asm volatile("red.global.add.v4.f32 [%0], {%1, %2, %3, %4};"
                         :: "l"((float*)&g_p[d.y]),
                            "f"(y1.x), "f"(y1.y), "f"(y1.z), "f"(y1.w) : "memory");
            atomicAdd(&g_dw[s.y].y, nd1);
        }
        if (ok2) {
            asm volatile("red.global.add.v4.f32 [%0], {%1, %2, %3, %4};"
                         :: "l"((float*)&g_p[d.z]),
                            "f"(y2.x), "f"(y2.y), "f"(y2.z), "f"(y2.w) : "memory");
            atomicAdd(&g_dw[s.z].y, nd2);
        }
        if (ok3) {
            asm volatile("red.global.add.v4.f32 [%0], {%1, %2, %3, %4};"
                         :: "l"((float*)&g_p[d.w]),
                            "f"(y3.x), "f"(y3.y), "f"(y3.z), "f"(y3.w) : "memory");
            atomicAdd(&g_dw[s.w].y, nd3);
        }
    }
    cudaTriggerProgrammaticLaunchCompletion();   // REDs issued; let k_node launch
}

// K4: node pass (transposed, butterfly reduce). PDL: W1/b1 smem staging
// pre-sync (overlaps k_edge drain); g_p/g_dw reads post-sync.
#define KN_BLOCKS 200
#define KN_THREADS 256
#define KN_SPAN (KN_BLOCKS * KN_THREADS)   // 51200
__global__ void __launch_bounds__(KN_THREADS, 2)
k_node(const float* __restrict__ W1, const float* __restrict__ b1) {
    __shared__ float4 sW[64];
    __shared__ float  sB[64];
    __shared__ float  sS[64];
    int tid = threadIdx.x;
    if (tid < 64) {
        sW[tid] = make_float4(W1[tid], W1[64 + tid], W1[128 + tid], W1[192 + tid]);
        sB[tid] = b1[tid];
        sS[tid] = 0.0f;
    }
    __syncthreads();
    cudaGridDependencySynchronize();       // wait for k_edge's p/dw updates

    int t  = blockIdx.x * KN_THREADS + tid;      // [0, 51200)
    int i1 = t + KN_SPAN;
    bool has1 = (i1 < N_NODES);

    float4 p0 = g_p[t];
    float2 d0 = g_dw[t];
    float4 p1 = make_float4(0.f, 0.f, 0.f, 0.f);
    float2 d1 = make_float2(0.f, 0.f);
    if (has1) { p1 = g_p[i1]; d1 = g_dw[i1]; }

    float q0x = d0.x * p0.x, q0y = d0.x * p0.y, q0z = d0.x * p0.z, q0w = d0.x * p0.w;
    float q1x = d1.x * p1.x, q1y = d1.x * p1.y, q1z = d1.x * p1.z, q1w = d1.x * p1.w;
    float wn0 = d0.x * d0.y;
    float wn1 = d1.x * d1.y;

    float acc[64];
    #pragma unroll
    for (int j = 0; j < 64; j++) {
        float4 w = sW[j];
        float  b = sB[j];
        float z0 = fmaf(q0x, w.x, fmaf(q0y, w.y, fmaf(q0z, w.z, fmaf(q0w, w.w, b))));
        float z1 = fmaf(q1x, w.x, fmaf(q1y, w.y, fmaf(q1z, w.z, fmaf(q1w, w.w, b))));
        acc[j] = fmaf(wn0, fmaxf(z0, 0.f), wn1 * fmaxf(z1, 0.f));
    }

    int lane = tid & 31;
    #pragma unroll
    for (int k = 0; k < 32; k++) {
        float lo = acc[k], hi = acc[k + 32];
        bool up = (lane & 16);
        float keep = up ? hi : lo, give = up ? lo : hi;
        acc[k] = keep + __shfl_xor_sync(0xffffffffu, give, 16);
    }
    #pragma unroll
    for (int k = 0; k < 16; k++) {
        float lo = acc[k], hi = acc[k + 16];
        bool up = (lane & 8);
        float keep = up ? hi : lo, give = up ? lo : hi;
        acc[k] = keep + __shfl_xor_sync(0xffffffffu, give, 8);
    }
    #pragma unroll
    for (int k = 0; k < 8; k++) {
        float lo = acc[k], hi = acc[k + 8];
        bool up = (lane & 4);
        float keep = up ? hi : lo, give = up ? lo : hi;
        acc[k] = keep + __shfl_xor_sync(0xffffffffu, give, 4);
    }
    #pragma unroll
    for (int k = 0; k < 4; k++) {
        float lo = acc[k], hi = acc[k + 4];
        bool up = (lane & 2);
        float keep = up ? hi : lo, give = up ? lo : hi;
        acc[k] = keep + __shfl_xor_sync(0xffffffffu, give, 2);
    }
    #pragma unroll
    for (int k = 0; k < 2; k++) {
        float lo = acc[k], hi = acc[k + 2];
        bool up = (lane & 1);
        float keep = up ? hi : lo, give = up ? lo : hi;
        acc[k] = keep + __shfl_xor_sync(0xffffffffu, give, 1);
    }
    int j0 = 32 * ((lane >> 4) & 1) + 16 * ((lane >> 3) & 1)
           +  8 * ((lane >> 2) & 1) +  4 * ((lane >> 1) & 1)
           +  2 * (lane & 1);
    atomicAdd(&sS[j0],     acc[0]);
    atomicAdd(&sS[j0 + 1], acc[1]);
    __syncthreads();
    if (tid < 64) atomicAdd(&g_S[tid], sS[tid]);
    cudaTriggerProgrammaticLaunchCompletion();   // S updates issued
}

// K5: out[k] = (S @ W2)[k] / n + b2[k]. PDL: sync then read g_S.
__global__ void k_final(const float* __restrict__ W2,
                        const float* __restrict__ b2,
                        float* __restrict__ out) {
    cudaGridDependencySynchronize();
    __shared__ float sS[64];
    int t = threadIdx.x;               // 0..63
    sS[t] = g_S[t];
    __syncthreads();
    if (t < 32) {
        float s = 0.f;
        #pragma unroll
        for (int j = 0; j < 64; j++) s = fmaf(sS[j], W2[j * 32 + t], s);
        out[t] = s * (1.0f / (float)N_NODES) + b2[t];
    }
}

extern "C" void kernel_launch(void* const* d_in, const int* in_sizes, int n_in,
                              void* d_out, int out_size) {
    const float4* x  = (const float4*)d_in[0];   // [100000, 4] f32
    const int*    ei = (const int*)d_in[1];      // [2, E] int32
    const float*  W1 = (const float*)d_in[2];    // [4, 64]
    const float*  b1 = (const float*)d_in[3];    // [64]
    const float*  W2 = (const float*)d_in[4];    // [64, 32]
    const float*  b2 = (const float*)d_in[5];    // [32]
    float*        out = (float*)d_out;           // [32]

    int E  = in_sizes[1] / 2;
    int E4 = E / 4;                              // E = 3.2M, divisible by 4
    const int4* src4 = (const int4*)ei;
    const int4* dst4 = (const int4*)(ei + E);

    const int T = 256;
    int nb_nodes  = (N_NODES + T - 1) / T;
    int nb_edges4 = (E4 + T - 1) / T;

    // PDL: dependent kernels launch during predecessor's drain; their
    // cudaGridDependencySynchronize() enforces the data dependency.
    cudaLaunchAttribute pdlAttr[1];
    pdlAttr[0].id = cudaLaunchAttributeProgrammaticStreamSerialization;
    pdlAttr[0].val.programmaticStreamSerializationAllowed = 1;

    // K1: plain launch (head of chain)
    k_deg<<<nb_edges4, T>>>(dst4, E4);

    cudaLaunchConfig_t cfg = {};
    cfg.attrs = pdlAttr;
    cfg.numAttrs = 1;
    cfg.blockDim = dim3(T);

    cfg.gridDim = dim3(nb_nodes);
    cudaLaunchKernelEx(&cfg, k_prep, x);

    cfg.gridDim = dim3(nb_edges4);
    cudaLaunchKernelEx(&cfg, k_edge, src4, dst4, E4);

    cfg.gridDim = dim3(KN_BLOCKS);
    cfg.blockDim = dim3(KN_THREADS);
    cudaLaunchKernelEx(&cfg, k_node, W1, b1);

    cfg.gridDim = dim3(1);
    cfg.blockDim = dim3(64);
    cudaLaunchKernelEx(&cfg, k_final, W2, b2, out);
}